// round 5
// baseline (speedup 1.0000x reference)
#include <cuda_runtime.h>
#include <cuda_bf16.h>
#include <math.h>
#include <stdint.h>

// Problem constants (fixed shapes)
#define B    8
#define C    192
#define C2   384
#define NH   4
#define CH   48
#define H    128
#define WD   128
#define HW   16384
#define NCHUNK 16
#define CHUNK  1024

// ---------------- scratch (static __device__ arrays) ------------------------
__device__ float g_t1 [B * C2 * HW];
__device__ float g_kv [B * C2 * HW];
__device__ float g_t2 [B * C  * HW];
__device__ float g_q  [B * C  * HW];
__device__ float g_att[B * C  * HW];
__device__ float g_pS [B * NH * NCHUNK * CH * CH];
__device__ float g_pnq[B * NH * NCHUNK * CH];
__device__ float g_pnk[B * NH * NCHUNK * CH];
__device__ float g_attn[B * NH * CH * CH];
// transposed bf16 hi/lo activations: [B][HW][384] (hi 0:192, lo 192:384)
__device__ __nv_bfloat16 g_xt[(size_t)B * HW * 384];
// split weights: [Cout][384] bf16 (hi 0:192, lo 192:384)
__device__ __nv_bfloat16 g_w1[384 * 384];
__device__ __nv_bfloat16 g_w2[192 * 384];
__device__ __nv_bfloat16 g_w3[192 * 384];

// ---------------- PTX helpers (sm_103 baseline ISA only) --------------------
__device__ __forceinline__ uint32_t smem_u32(const void* p) {
    uint32_t a;
    asm("{ .reg .u64 t; cvta.to.shared.u64 t, %1; cvt.u32.u64 %0, t; }"
        : "=r"(a) : "l"(p));
    return a;
}
#define CP16(d, s) \
    asm volatile("cp.async.cg.shared.global [%0], [%1], 16;" :: "r"(d), "l"(s))
#define CP_COMMIT() asm volatile("cp.async.commit_group;")
#define CP_WAIT(n)  asm volatile("cp.async.wait_group %0;" :: "n"(n))

__device__ __forceinline__ void ldm4(uint32_t* r, uint32_t addr) {
    asm volatile("ldmatrix.sync.aligned.m8n8.x4.shared.b16 {%0,%1,%2,%3}, [%4];"
        : "=r"(r[0]), "=r"(r[1]), "=r"(r[2]), "=r"(r[3]) : "r"(addr));
}
__device__ __forceinline__ void mma_bf16(float* c, const uint32_t* a,
                                         const uint32_t* b) {
    asm volatile(
        "mma.sync.aligned.m16n8k16.row.col.f32.bf16.bf16.f32 "
        "{%0,%1,%2,%3}, {%4,%5,%6,%7}, {%8,%9}, {%0,%1,%2,%3};"
        : "+f"(c[0]), "+f"(c[1]), "+f"(c[2]), "+f"(c[3])
        : "r"(a[0]), "r"(a[1]), "r"(a[2]), "r"(a[3]), "r"(b[0]), "r"(b[1]));
}

// ---------------- weight split: W[Cout][192] -> [Cout][384] bf16 ------------
__global__ void prep_w_kernel(const float* __restrict__ w,
                              __nv_bfloat16* __restrict__ o) {
    int m = blockIdx.x;
    int k = threadIdx.x;
    float v = w[(size_t)m * 192 + k];
    __nv_bfloat16 hi = __float2bfloat16(v);
    __nv_bfloat16 lo = __float2bfloat16(v - __bfloat162float(hi));
    o[(size_t)m * 384 + k]       = hi;
    o[(size_t)m * 384 + 192 + k] = lo;
}

// ---------------- activation split+transpose: [B,192,HW] -> [B,HW,384] bf16 -
__global__ __launch_bounds__(256) void split_transpose_kernel(
    const float* __restrict__ in, __nv_bfloat16* __restrict__ out)
{
    const int n0 = blockIdx.x * 64;
    const int b  = blockIdx.y;
    __shared__ __nv_bfloat16 sT[64][390];

    const float* ip = in + (size_t)b * 192 * HW + n0;
    const int nn = threadIdx.x & 63;
    const int kq = threadIdx.x >> 6;

    for (int k0 = 0; k0 < 192; k0 += 8) {
        int k = k0 + kq * 2;
        float v0 = ip[(size_t)k * HW + nn];
        float v1 = ip[(size_t)(k + 1) * HW + nn];
        __nv_bfloat16 h0 = __float2bfloat16(v0);
        __nv_bfloat16 h1 = __float2bfloat16(v1);
        __nv_bfloat16 l0 = __float2bfloat16(v0 - __bfloat162float(h0));
        __nv_bfloat16 l1 = __float2bfloat16(v1 - __bfloat162float(h1));
        *(__nv_bfloat162*)(&sT[nn][k])       = __nv_bfloat162(h0, h1);
        *(__nv_bfloat162*)(&sT[nn][192 + k]) = __nv_bfloat162(l0, l1);
    }
    __syncthreads();

    uint32_t* op = (uint32_t*)(out + ((size_t)b * HW + n0) * 384);
    for (int idx = threadIdx.x; idx < 64 * 192; idx += 256) {
        int r = idx / 192, u = idx - r * 192;
        op[(size_t)r * 192 + u] = *(const uint32_t*)(&sT[r][u * 2]);
    }
}

// ---------------- HMMA GEMM: out[b,m,n] = sum_k W[m,k]*X[k,n] ----------------
// Block tile: 128 pixels x 192 couts. Virtual K = 576 (3 hi/lo terms x 192),
// 9 chunks of 64. 3-stage cp.async pipeline, one barrier per iteration.
// Epilogue staged through smem for coalesced float4 stores.
#define APITCH  144                        // 128B row + 16B pad (ldmatrix-safe)
#define A_STAGE (128 * APITCH)             // 18432
#define B_STAGE (192 * APITCH)             // 27648
#define STAGE_SZ (A_STAGE + B_STAGE)       // 46080
#define NSTAGE  3
#define PITCHC  132                        // floats
#define GSM_TOTAL (NSTAGE * STAGE_SZ)      // 138240 (> 192*132*4 = 101376)

__device__ __forceinline__ void g_load_chunk(
    uint32_t sb, const char* abase, const char* bbase, int tid, int c, int stage)
{
    const int term = c / 3;
    const int kk = (c - term * 3) * 64;
    const int aoff = ((term == 2 ? 192 : 0) + kk) * 2;  // X uses lo on term 2
    const int boff = ((term == 1 ? 192 : 0) + kk) * 2;  // W uses lo on term 1
    const uint32_t sa  = sb + stage * STAGE_SZ;
    const uint32_t sbm = sa + A_STAGE;
#pragma unroll
    for (int p = 0; p < 4; p++) {                       // A: 128 rows x 8 segs
        int idx = p * 256 + tid;
        int row = idx >> 3, q = idx & 7;
        CP16(sa + row * APITCH + q * 16,
             abase + (size_t)row * 768 + aoff + q * 16);
    }
#pragma unroll
    for (int p = 0; p < 6; p++) {                       // B: 192 rows x 8 segs
        int idx = p * 256 + tid;
        int row = idx >> 3, q = idx & 7;
        CP16(sbm + row * APITCH + q * 16,
             bbase + (size_t)row * 768 + boff + q * 16);
    }
    CP_COMMIT();
}

__global__ __launch_bounds__(256) void gemm_hmma_kernel(
    const __nv_bfloat16* __restrict__ xt, const __nv_bfloat16* __restrict__ wsp,
    float* __restrict__ out, int Cout)
{
    extern __shared__ char smem[];
    const uint32_t sb = smem_u32(smem);
    const int pix0  = blockIdx.x * 128;
    const int cout0 = blockIdx.y * 192;
    const int b     = blockIdx.z;
    const int tid   = threadIdx.x;
    const int lane  = tid & 31, wid = tid >> 5;
    const int wy = wid & 1;    // pixel half (64 each)
    const int wx = wid >> 1;   // cout quarter (48 each)

    const char* abase = (const char*)(xt + ((size_t)(b * HW) + pix0) * 384);
    const char* bbase = (const char*)(wsp + (size_t)cout0 * 384);

    float acc[4][6][4];
#pragma unroll
    for (int i = 0; i < 4; i++)
#pragma unroll
        for (int j = 0; j < 6; j++)
#pragma unroll
            for (int t = 0; t < 4; t++) acc[i][j][t] = 0.0f;

    g_load_chunk(sb, abase, bbase, tid, 0, 0);
    g_load_chunk(sb, abase, bbase, tid, 1, 1);

    for (int c = 0; c < 9; c++) {
        if (c + 2 < 9) {
            CP_WAIT(1);                 // chunk c complete
            __syncthreads();            // stage (c+2)%3 free to overwrite
            g_load_chunk(sb, abase, bbase, tid, c + 2, (c + 2) % NSTAGE);
        } else {
            CP_WAIT(0);
            __syncthreads();
        }

        const uint32_t sa  = sb + (c % NSTAGE) * STAGE_SZ;
        const uint32_t sbm = sa + A_STAGE;
#pragma unroll
        for (int ks = 0; ks < 4; ks++) {
            uint32_t afr[4][4];
#pragma unroll
            for (int mi = 0; mi < 4; mi++)
                ldm4(afr[mi], sa + (wy * 64 + mi * 16 + (lane & 15)) * APITCH
                              + ks * 32 + (lane >> 4) * 16);
            uint32_t bfr[3][4];
#pragma unroll
            for (int nj = 0; nj < 3; nj++)
                ldm4(bfr[nj], sbm + (wx * 48 + nj * 16 + (lane & 7)
                                     + (lane >> 4) * 8) * APITCH
                              + ks * 32 + ((lane >> 3) & 1) * 16);
#pragma unroll
            for (int mi = 0; mi < 4; mi++)
#pragma unroll
                for (int nj = 0; nj < 3; nj++) {
                    mma_bf16(acc[mi][nj * 2],     afr[mi], &bfr[nj][0]);
                    mma_bf16(acc[mi][nj * 2 + 1], afr[mi], &bfr[nj][2]);
                }
        }
    }

    // ---- epilogue: fragments -> smem [cout][pixel] -> coalesced float4 ----
    __syncthreads();
    float* sC = (float*)smem;
    const int prow = lane >> 2;
    const int ccol = (lane & 3) * 2;
#pragma unroll
    for (int mi = 0; mi < 4; mi++) {
        const int p = wy * 64 + mi * 16 + prow;
#pragma unroll
        for (int ni = 0; ni < 6; ni++) {
            const int co = wx * 48 + ni * 8 + ccol;
            sC[co * PITCHC + p]           = acc[mi][ni][0];
            sC[(co + 1) * PITCHC + p]     = acc[mi][ni][1];
            sC[co * PITCHC + p + 8]       = acc[mi][ni][2];
            sC[(co + 1) * PITCHC + p + 8] = acc[mi][ni][3];
        }
    }
    __syncthreads();

    float* ob = out + ((size_t)b * Cout + cout0) * HW + pix0;
#pragma unroll
    for (int e = 0; e < 24; e++) {
        int idx = tid + e * 256;            // 0..6143 = 192 rows x 32 float4
        int r = idx >> 5, u = idx & 31;
        *(float4*)(ob + (size_t)r * HW + u * 4) =
            *(const float4*)(&sC[r * PITCHC + u * 4]);
    }
}

// ---------------- depthwise 3x3, SAME padding --------------------------------
__global__ __launch_bounds__(128) void dwconv3x3_kernel(
    const float* __restrict__ in, const float* __restrict__ w9,
    float* __restrict__ out, int Cc)
{
    const int y0 = blockIdx.x * 8;
    const int c  = blockIdx.y;
    const int b  = blockIdx.z;
    const int x  = threadIdx.x;

    __shared__ float s[10][130];
    const float* ip = in  + ((size_t)b * Cc + c) * HW;
    float*       op = out + ((size_t)b * Cc + c) * HW;

    float wr[9];
#pragma unroll
    for (int t = 0; t < 9; t++) wr[t] = w9[c * 9 + t];

#pragma unroll
    for (int r = 0; r < 10; r++) {
        int yy = y0 - 1 + r;
        s[r][x + 1] = (yy >= 0 && yy < H) ? ip[yy * WD + x] : 0.0f;
    }
    if (x == 0) {
#pragma unroll
        for (int r = 0; r < 10; r++) { s[r][0] = 0.0f; s[r][129] = 0.0f; }
    }
    __syncthreads();

#pragma unroll
    for (int ry = 0; ry < 8; ry++) {
        float a =
            s[ry + 0][x + 0] * wr[0] + s[ry + 0][x + 1] * wr[1] + s[ry + 0][x + 2] * wr[2] +
            s[ry + 1][x + 0] * wr[3] + s[ry + 1][x + 1] * wr[4] + s[ry + 1][x + 2] * wr[5] +
            s[ry + 2][x + 0] * wr[6] + s[ry + 2][x + 1] * wr[7] + s[ry + 2][x + 2] * wr[8];
        op[(y0 + ry) * WD + x] = a;
    }
}

// ---------------- split-K Gram + norms ---------------------------------------
__global__ __launch_bounds__(256) void gram_kernel()
{
    const int ck = blockIdx.x, h = blockIdx.y, b = blockIdx.z;
    const int tid = threadIdx.x;
    const int tx = tid & 15, ty = tid >> 4;

    const float* qp = g_q  + ((size_t)b * C  + h * CH) * HW + ck * CHUNK;
    const float* kp = g_kv + ((size_t)b * C2 + h * CH) * HW + ck * CHUNK;

    __shared__ float sQ[32][49];
    __shared__ float sK[32][49];

    float acc[3][3];
#pragma unroll
    for (int i = 0; i < 3; i++)
#pragma unroll
        for (int j = 0; j < 3; j++) acc[i][j] = 0.0f;
    float sq[3] = {0.f, 0.f, 0.f}, sk2[3] = {0.f, 0.f, 0.f};

    for (int nb = 0; nb < CHUNK; nb += 32) {
#pragma unroll
        for (int e = 0; e < 6; e++) {
            int idx = tid + e * 256;
            int cc = idx >> 5, nn = idx & 31;
            sQ[nn][cc] = qp[(size_t)cc * HW + nb + nn];
            sK[nn][cc] = kp[(size_t)cc * HW + nb + nn];
        }
        __syncthreads();
#pragma unroll
        for (int kk = 0; kk < 32; kk++) {
            float a0 = sQ[kk][ty * 3 + 0];
            float a1 = sQ[kk][ty * 3 + 1];
            float a2 = sQ[kk][ty * 3 + 2];
            float b0 = sK[kk][tx * 3 + 0];
            float b1 = sK[kk][tx * 3 + 1];
            float b2 = sK[kk][tx * 3 + 2];
            acc[0][0] += a0 * b0; acc[0][1] += a0 * b1; acc[0][2] += a0 * b2;
            acc[1][0] += a1 * b0; acc[1][1] += a1 * b1; acc[1][2] += a1 * b2;
            acc[2][0] += a2 * b0; acc[2][1] += a2 * b1; acc[2][2] += a2 * b2;
            if (tx == 0) { sq[0]  += a0 * a0; sq[1]  += a1 * a1; sq[2]  += a2 * a2; }
            if (ty == 0) { sk2[0] += b0 * b0; sk2[1] += b1 * b1; sk2[2] += b2 * b2; }
        }
        __syncthreads();
    }

    const int base = (b * NH + h) * NCHUNK + ck;
    float* ps = g_pS + (size_t)base * (CH * CH);
#pragma unroll
    for (int i = 0; i < 3; i++)
#pragma unroll
        for (int j = 0; j < 3; j++)
            ps[(ty * 3 + i) * CH + tx * 3 + j] = acc[i][j];
    if (tx == 0) {
#pragma unroll
        for (int i = 0; i < 3; i++) g_pnq[base * CH + ty * 3 + i] = sq[i];
    }
    if (ty == 0) {
#pragma unroll
        for (int j = 0; j < 3; j++) g_pnk[base * CH + tx * 3 + j] = sk2[j];
    }
}

// ---------------- reduce, normalize, temperature, softmax --------------------
__global__ __launch_bounds__(256) void reduce_softmax_kernel(
    const float* __restrict__ temperature)
{
    const int bh = blockIdx.x;
    const int h  = bh & (NH - 1);
    const int tid = threadIdx.x;

    __shared__ float sS[CH * CH];
    __shared__ float snq[CH], snk[CH];

    for (int idx = tid; idx < CH * CH; idx += 256) {
        float s = 0.0f;
        for (int ck = 0; ck < NCHUNK; ck++)
            s += g_pS[(size_t)(bh * NCHUNK + ck) * (CH * CH) + idx];
        sS[idx] = s;
    }
    if (tid < CH) {
        float s = 0.0f;
        for (int ck = 0; ck < NCHUNK; ck++)
            s += g_pnq[(bh * NCHUNK + ck) * CH + tid];
        snq[tid] = fmaxf(sqrtf(s), 1e-12f);
    } else if (tid >= 64 && tid < 64 + CH) {
        int d = tid - 64;
        float s = 0.0f;
        for (int ck = 0; ck < NCHUNK; ck++)
            s += g_pnk[(bh * NCHUNK + ck) * CH + d];
        snk[d] = fmaxf(sqrtf(s), 1e-12f);
    }
    __syncthreads();

    const float t = temperature[h];
    for (int idx = tid; idx < CH * CH; idx += 256) {
        int cc = idx / CH, d = idx - cc * CH;
        sS[idx] = sS[idx] * t / (snq[cc] * snk[d]);
    }
    __syncthreads();

    if (tid < CH) {
        const int cc = tid;
        float m = -1e30f;
        for (int d = 0; d < CH; d++) m = fmaxf(m, sS[cc * CH + d]);
        float sum = 0.0f;
        for (int d = 0; d < CH; d++) {
            float e = expf(sS[cc * CH + d] - m);
            sS[cc * CH + d] = e;
            sum += e;
        }
        float inv = 1.0f / sum;
        for (int d = 0; d < CH; d++)
            g_attn[(size_t)bh * (CH * CH) + cc * CH + d] = sS[cc * CH + d] * inv;
    }
}

// ---------------- out[c,n] = sum_d attn[c,d] * v[d,n] ------------------------
__global__ __launch_bounds__(256) void attnv_kernel()
{
    const int n0 = blockIdx.x * 128;
    const int h  = blockIdx.y, b = blockIdx.z;
    const int tid = threadIdx.x;
    const int tx = tid & 31, ty = tid >> 5;

    __shared__ float sA[CH][CH];
    __shared__ __align__(16) float sV[CH][128];

    const float* vp = g_kv + ((size_t)b * C2 + C + h * CH) * HW + n0;
    const float* ap = g_attn + (size_t)(b * NH + h) * (CH * CH);

    for (int idx = tid; idx < CH * CH; idx += 256)
        sA[idx / CH][idx % CH] = ap[idx];
#pragma unroll
    for (int e = 0; e < 6; e++) {
        int idx = tid + e * 256;
        int d = idx >> 5, nv = idx & 31;
        ((float4*)(&sV[d][0]))[nv] = ((const float4*)(vp + (size_t)d * HW))[nv];
    }
    __syncthreads();

    float4 acc[6];
#pragma unroll
    for (int i = 0; i < 6; i++) acc[i] = make_float4(0.f, 0.f, 0.f, 0.f);

    for (int d = 0; d < CH; d++) {
        float4 vv = ((const float4*)(&sV[d][0]))[tx];
#pragma unroll
        for (int i = 0; i < 6; i++) {
            float a = sA[ty * 6 + i][d];
            acc[i].x += a * vv.x; acc[i].y += a * vv.y;
            acc[i].z += a * vv.z; acc[i].w += a * vv.w;
        }
    }

    float* op = g_att + ((size_t)b * C + h * CH + ty * 6) * HW + n0 + tx * 4;
#pragma unroll
    for (int i = 0; i < 6; i++)
        *((float4*)(op + (size_t)i * HW)) = acc[i];
}

// ---------------- launcher ----------------------------------------------------
extern "C" void kernel_launch(void* const* d_in, const int* in_sizes, int n_in,
                              void* d_out, int out_size)
{
    const float* x           = (const float*)d_in[0];
    const float* y           = (const float*)d_in[1];
    const float* w_qkv       = (const float*)d_in[2];
    const float* w_qkv_dw    = (const float*)d_in[3];
    const float* w_query     = (const float*)d_in[4];
    const float* w_query_dw  = (const float*)d_in[5];
    const float* w_proj      = (const float*)d_in[6];
    const float* temperature = (const float*)d_in[7];
    float* out = (float*)d_out;

    float *t1, *kv, *t2, *q, *att;
    __nv_bfloat16 *xt, *w1, *w2, *w3;
    cudaGetSymbolAddress((void**)&t1,  g_t1);
    cudaGetSymbolAddress((void**)&kv,  g_kv);
    cudaGetSymbolAddress((void**)&t2,  g_t2);
    cudaGetSymbolAddress((void**)&q,   g_q);
    cudaGetSymbolAddress((void**)&att, g_att);
    cudaGetSymbolAddress((void**)&xt,  g_xt);
    cudaGetSymbolAddress((void**)&w1,  g_w1);
    cudaGetSymbolAddress((void**)&w2,  g_w2);
    cudaGetSymbolAddress((void**)&w3,  g_w3);

    static int smem_set = 0;
    if (!smem_set) {
        cudaFuncSetAttribute(gemm_hmma_kernel,
                             cudaFuncAttributeMaxDynamicSharedMemorySize, GSM_TOTAL);
        smem_set = 1;
    }

    // weight hi/lo split (tiny)
    prep_w_kernel<<<384, 192>>>(w_qkv,   w1);
    prep_w_kernel<<<192, 192>>>(w_query, w2);
    prep_w_kernel<<<192, 192>>>(w_proj,  w3);

    // conv1: x -> t1 [8,384,HW]
    split_transpose_kernel<<<dim3(HW / 64, B), 256>>>(x, xt);
    gemm_hmma_kernel<<<dim3(HW / 128, 2, B), 256, GSM_TOTAL>>>(xt, w1, t1, 384);

    // conv2: y -> t2 [8,192,HW]
    split_transpose_kernel<<<dim3(HW / 64, B), 256>>>(y, xt);
    gemm_hmma_kernel<<<dim3(HW / 128, 1, B), 256, GSM_TOTAL>>>(xt, w2, t2, 192);

    // depthwise 3x3
    dwconv3x3_kernel<<<dim3(H / 8, C2, B), 128>>>(t1, w_qkv_dw, kv, C2);
    dwconv3x3_kernel<<<dim3(H / 8, C, B), 128>>>(t2, w_query_dw, q, C);

    // attention
    gram_kernel<<<dim3(NCHUNK, NH, B), 256>>>();
    reduce_softmax_kernel<<<B * NH, 256>>>(temperature);
    attnv_kernel<<<dim3(HW / 128, NH, B), 256>>>();

    // conv3: att -> out
    split_transpose_kernel<<<dim3(HW / 64, B), 256>>>(att, xt);
    gemm_hmma_kernel<<<dim3(HW / 128, 1, B), 256, GSM_TOTAL>>>(xt, w3, out, 192);
}

// round 6
// speedup vs baseline: 1.0330x; 1.0330x over previous
#include <cuda_runtime.h>
#include <cuda_bf16.h>
#include <math.h>
#include <stdint.h>

// Problem constants (fixed shapes)
#define B    8
#define C    192
#define C2   384
#define NH   4
#define CH   48
#define H    128
#define WD   128
#define HW   16384
#define NCHUNK 16
#define CHUNK  1024

// ---------------- scratch (static __device__ arrays) ------------------------
__device__ float g_t1 [B * C2 * HW];
__device__ float g_kv [B * C2 * HW];
__device__ float g_t2 [B * C  * HW];
__device__ float g_q  [B * C  * HW];
__device__ float g_pS [B * NH * NCHUNK * CH * CH];
__device__ float g_pnq[B * NH * NCHUNK * CH];
__device__ float g_pnk[B * NH * NCHUNK * CH];
__device__ float g_attn[B * NH * CH * CH];
// transposed bf16 hi/lo activations: [B][HW][384] (hi 0:192, lo 192:384)
__device__ __nv_bfloat16 g_xta[(size_t)B * HW * 384];  // x, later attn output
__device__ __nv_bfloat16 g_xtb[(size_t)B * HW * 384];  // y
// split weights: [Cout][384] bf16 (hi 0:192, lo 192:384)
__device__ __nv_bfloat16 g_w1[384 * 384];
__device__ __nv_bfloat16 g_w2[192 * 384];
__device__ __nv_bfloat16 g_w3[192 * 384];

// ---------------- PTX helpers (sm_103 baseline ISA only) --------------------
__device__ __forceinline__ uint32_t smem_u32(const void* p) {
    uint32_t a;
    asm("{ .reg .u64 t; cvta.to.shared.u64 t, %1; cvt.u32.u64 %0, t; }"
        : "=r"(a) : "l"(p));
    return a;
}
#define CP16(d, s) \
    asm volatile("cp.async.cg.shared.global [%0], [%1], 16;" :: "r"(d), "l"(s))
#define CP_COMMIT() asm volatile("cp.async.commit_group;")
#define CP_WAIT(n)  asm volatile("cp.async.wait_group %0;" :: "n"(n))

__device__ __forceinline__ void ldm4(uint32_t* r, uint32_t addr) {
    asm volatile("ldmatrix.sync.aligned.m8n8.x4.shared.b16 {%0,%1,%2,%3}, [%4];"
        : "=r"(r[0]), "=r"(r[1]), "=r"(r[2]), "=r"(r[3]) : "r"(addr));
}
__device__ __forceinline__ void mma_bf16(float* c, const uint32_t* a,
                                         const uint32_t* b) {
    asm volatile(
        "mma.sync.aligned.m16n8k16.row.col.f32.bf16.bf16.f32 "
        "{%0,%1,%2,%3}, {%4,%5,%6,%7}, {%8,%9}, {%0,%1,%2,%3};"
        : "+f"(c[0]), "+f"(c[1]), "+f"(c[2]), "+f"(c[3])
        : "r"(a[0]), "r"(a[1]), "r"(a[2]), "r"(a[3]), "r"(b[0]), "r"(b[1]));
}

// ---------------- weight split: W[Cout][192] -> [Cout][384] bf16 ------------
__global__ void prep_w_kernel(const float* __restrict__ w,
                              __nv_bfloat16* __restrict__ o) {
    int m = blockIdx.x;
    int k = threadIdx.x;
    float v = w[(size_t)m * 192 + k];
    __nv_bfloat16 hi = __float2bfloat16(v);
    __nv_bfloat16 lo = __float2bfloat16(v - __bfloat162float(hi));
    o[(size_t)m * 384 + k]       = hi;
    o[(size_t)m * 384 + 192 + k] = lo;
}

// ---------------- activation split+transpose: [B,192,HW] -> [B,HW,384] bf16 -
__global__ __launch_bounds__(256) void split_transpose_kernel(
    const float* __restrict__ in, __nv_bfloat16* __restrict__ out)
{
    const int n0 = blockIdx.x * 64;
    const int b  = blockIdx.y;
    __shared__ __nv_bfloat16 sT[64][390];

    const float* ip = in + (size_t)b * 192 * HW + n0;
    const int nn = threadIdx.x & 63;
    const int kq = threadIdx.x >> 6;

    for (int k0 = 0; k0 < 192; k0 += 8) {
        int k = k0 + kq * 2;
        float v0 = ip[(size_t)k * HW + nn];
        float v1 = ip[(size_t)(k + 1) * HW + nn];
        __nv_bfloat16 h0 = __float2bfloat16(v0);
        __nv_bfloat16 h1 = __float2bfloat16(v1);
        __nv_bfloat16 l0 = __float2bfloat16(v0 - __bfloat162float(h0));
        __nv_bfloat16 l1 = __float2bfloat16(v1 - __bfloat162float(h1));
        *(__nv_bfloat162*)(&sT[nn][k])       = __nv_bfloat162(h0, h1);
        *(__nv_bfloat162*)(&sT[nn][192 + k]) = __nv_bfloat162(l0, l1);
    }
    __syncthreads();

    uint32_t* op = (uint32_t*)(out + ((size_t)b * HW + n0) * 384);
    for (int idx = threadIdx.x; idx < 64 * 192; idx += 256) {
        int r = idx / 192, u = idx - r * 192;
        op[(size_t)r * 192 + u] = *(const uint32_t*)(&sT[r][u * 2]);
    }
}

// ---------------- HMMA GEMM: out[b,m,n] = sum_k W[m,k]*X[k,n] ----------------
// Block tile: 128 pixels x 192 couts. Virtual K = 576 (3 hi/lo terms x 192),
// 18 chunks of 32. 3-stage cp.async ring, ONE barrier per iteration.
#define APITCH  80
#define A_STAGE (128 * APITCH)   // 10240
#define B_STAGE (192 * APITCH)   // 15360
#define STG     (A_STAGE + B_STAGE)  // 25600
#define NSTAGE  3
#define GSM_TOTAL (NSTAGE * STG)     // 76800

__device__ __forceinline__ void g_load_chunk(
    uint32_t sb, const char* abase, const char* bbase, int tid, int c, int stage)
{
    const int term = c / 6;
    const int kk = (c - term * 6) * 32;
    const int aoff = ((term == 2 ? 192 : 0) + kk) * 2;  // X uses lo on term 2
    const int boff = ((term == 1 ? 192 : 0) + kk) * 2;  // W uses lo on term 1
    const uint32_t sa  = sb + stage * STG;
    const uint32_t sbm = sa + A_STAGE;
#pragma unroll
    for (int p = 0; p < 2; p++) {                       // A: 128 rows x 4 segs
        int idx = p * 256 + tid;
        int row = idx >> 2, q = idx & 3;
        CP16(sa + row * APITCH + q * 16,
             abase + (size_t)row * 768 + aoff + q * 16);
    }
#pragma unroll
    for (int p = 0; p < 3; p++) {                       // B: 192 rows x 4 segs
        int idx = p * 256 + tid;
        int row = idx >> 2, q = idx & 3;
        CP16(sbm + row * APITCH + q * 16,
             bbase + (size_t)row * 768 + boff + q * 16);
    }
    CP_COMMIT();
}

__global__ __launch_bounds__(256) void gemm_hmma_kernel(
    const __nv_bfloat16* __restrict__ xt, const __nv_bfloat16* __restrict__ wsp,
    float* __restrict__ out, int Cout)
{
    extern __shared__ char smem[];
    const uint32_t sb = smem_u32(smem);
    const int pix0  = blockIdx.x * 128;
    const int cout0 = blockIdx.y * 192;
    const int b     = blockIdx.z;
    const int tid   = threadIdx.x;
    const int lane  = tid & 31, wid = tid >> 5;
    const int wy = wid & 1;    // pixel half (64 each)
    const int wx = wid >> 1;   // cout quarter (48 each)

    const char* abase = (const char*)(xt + ((size_t)(b * HW) + pix0) * 384);
    const char* bbase = (const char*)(wsp + (size_t)cout0 * 384);

    float acc[4][6][4];
#pragma unroll
    for (int i = 0; i < 4; i++)
#pragma unroll
        for (int j = 0; j < 6; j++)
#pragma unroll
            for (int t = 0; t < 4; t++) acc[i][j][t] = 0.0f;

    g_load_chunk(sb, abase, bbase, tid, 0, 0);
    g_load_chunk(sb, abase, bbase, tid, 1, 1);

    for (int c = 0; c < 18; c++) {
        if (c + 2 < 18) {
            CP_WAIT(1);                 // chunk c landed
            __syncthreads();            // all warps done with stage (c+2)%3
            g_load_chunk(sb, abase, bbase, tid, c + 2, (c + 2) % NSTAGE);
        } else {
            CP_WAIT(0);
            __syncthreads();
        }

        const uint32_t sa  = sb + (c % NSTAGE) * STG;
        const uint32_t sbm = sa + A_STAGE;
#pragma unroll
        for (int ks = 0; ks < 2; ks++) {
            uint32_t afr[4][4];
#pragma unroll
            for (int mi = 0; mi < 4; mi++)
                ldm4(afr[mi], sa + (wy * 64 + mi * 16 + (lane & 15)) * APITCH
                              + ks * 32 + (lane >> 4) * 16);
            uint32_t bfr[3][4];
#pragma unroll
            for (int nj = 0; nj < 3; nj++)
                ldm4(bfr[nj], sbm + (wx * 48 + nj * 16 + (lane & 7)
                                     + (lane >> 4) * 8) * APITCH
                              + ks * 32 + ((lane >> 3) & 1) * 16);
#pragma unroll
            for (int mi = 0; mi < 4; mi++)
#pragma unroll
                for (int nj = 0; nj < 3; nj++) {
                    mma_bf16(acc[mi][nj * 2],     afr[mi], &bfr[nj][0]);
                    mma_bf16(acc[mi][nj * 2 + 1], afr[mi], &bfr[nj][2]);
                }
        }
    }

    // epilogue: direct stores (sector-efficient: 8 lanes -> 8 consecutive floats)
    const int prow = lane >> 2;
    const int ccol = (lane & 3) * 2;
#pragma unroll
    for (int mi = 0; mi < 4; mi++) {
        const int p = pix0 + wy * 64 + mi * 16 + prow;
#pragma unroll
        for (int ni = 0; ni < 6; ni++) {
            const int co = cout0 + wx * 48 + ni * 8 + ccol;
            float* o0 = out + ((size_t)b * Cout + co) * HW + p;
            o0[0]      = acc[mi][ni][0];
            o0[HW]     = acc[mi][ni][1];
            o0[8]      = acc[mi][ni][2];
            o0[HW + 8] = acc[mi][ni][3];
        }
    }
}

// ---------------- depthwise 3x3, SAME padding --------------------------------
__global__ __launch_bounds__(128) void dwconv3x3_kernel(
    const float* __restrict__ in, const float* __restrict__ w9,
    float* __restrict__ out, int Cc)
{
    const int y0 = blockIdx.x * 8;
    const int c  = blockIdx.y;
    const int b  = blockIdx.z;
    const int x  = threadIdx.x;

    __shared__ float s[10][130];
    const float* ip = in  + ((size_t)b * Cc + c) * HW;
    float*       op = out + ((size_t)b * Cc + c) * HW;

    float wr[9];
#pragma unroll
    for (int t = 0; t < 9; t++) wr[t] = w9[c * 9 + t];

#pragma unroll
    for (int r = 0; r < 10; r++) {
        int yy = y0 - 1 + r;
        s[r][x + 1] = (yy >= 0 && yy < H) ? ip[yy * WD + x] : 0.0f;
    }
    if (x == 0) {
#pragma unroll
        for (int r = 0; r < 10; r++) { s[r][0] = 0.0f; s[r][129] = 0.0f; }
    }
    __syncthreads();

#pragma unroll
    for (int ry = 0; ry < 8; ry++) {
        float a =
            s[ry + 0][x + 0] * wr[0] + s[ry + 0][x + 1] * wr[1] + s[ry + 0][x + 2] * wr[2] +
            s[ry + 1][x + 0] * wr[3] + s[ry + 1][x + 1] * wr[4] + s[ry + 1][x + 2] * wr[5] +
            s[ry + 2][x + 0] * wr[6] + s[ry + 2][x + 1] * wr[7] + s[ry + 2][x + 2] * wr[8];
        op[(y0 + ry) * WD + x] = a;
    }
}

// ---------------- split-K Gram + norms ---------------------------------------
__global__ __launch_bounds__(256) void gram_kernel()
{
    const int ck = blockIdx.x, h = blockIdx.y, b = blockIdx.z;
    const int tid = threadIdx.x;
    const int tx = tid & 15, ty = tid >> 4;

    const float* qp = g_q  + ((size_t)b * C  + h * CH) * HW + ck * CHUNK;
    const float* kp = g_kv + ((size_t)b * C2 + h * CH) * HW + ck * CHUNK;

    __shared__ float sQ[32][49];
    __shared__ float sK[32][49];

    float acc[3][3];
#pragma unroll
    for (int i = 0; i < 3; i++)
#pragma unroll
        for (int j = 0; j < 3; j++) acc[i][j] = 0.0f;
    float sq[3] = {0.f, 0.f, 0.f}, sk2[3] = {0.f, 0.f, 0.f};

    for (int nb = 0; nb < CHUNK; nb += 32) {
#pragma unroll
        for (int e = 0; e < 6; e++) {
            int idx = tid + e * 256;
            int cc = idx >> 5, nn = idx & 31;
            sQ[nn][cc] = qp[(size_t)cc * HW + nb + nn];
            sK[nn][cc] = kp[(size_t)cc * HW + nb + nn];
        }
        __syncthreads();
#pragma unroll
        for (int kk = 0; kk < 32; kk++) {
            float a0 = sQ[kk][ty * 3 + 0];
            float a1 = sQ[kk][ty * 3 + 1];
            float a2 = sQ[kk][ty * 3 + 2];
            float b0 = sK[kk][tx * 3 + 0];
            float b1 = sK[kk][tx * 3 + 1];
            float b2 = sK[kk][tx * 3 + 2];
            acc[0][0] += a0 * b0; acc[0][1] += a0 * b1; acc[0][2] += a0 * b2;
            acc[1][0] += a1 * b0; acc[1][1] += a1 * b1; acc[1][2] += a1 * b2;
            acc[2][0] += a2 * b0; acc[2][1] += a2 * b1; acc[2][2] += a2 * b2;
            if (tx == 0) { sq[0]  += a0 * a0; sq[1]  += a1 * a1; sq[2]  += a2 * a2; }
            if (ty == 0) { sk2[0] += b0 * b0; sk2[1] += b1 * b1; sk2[2] += b2 * b2; }
        }
        __syncthreads();
    }

    const int base = (b * NH + h) * NCHUNK + ck;
    float* ps = g_pS + (size_t)base * (CH * CH);
#pragma unroll
    for (int i = 0; i < 3; i++)
#pragma unroll
        for (int j = 0; j < 3; j++)
            ps[(ty * 3 + i) * CH + tx * 3 + j] = acc[i][j];
    if (tx == 0) {
#pragma unroll
        for (int i = 0; i < 3; i++) g_pnq[base * CH + ty * 3 + i] = sq[i];
    }
    if (ty == 0) {
#pragma unroll
        for (int j = 0; j < 3; j++) g_pnk[base * CH + tx * 3 + j] = sk2[j];
    }
}

// ---------------- reduce, normalize, temperature, softmax --------------------
__global__ __launch_bounds__(256) void reduce_softmax_kernel(
    const float* __restrict__ temperature)
{
    const int bh = blockIdx.x;
    const int h  = bh & (NH - 1);
    const int tid = threadIdx.x;

    __shared__ float sS[CH * CH];
    __shared__ float snq[CH], snk[CH];

    for (int idx = tid; idx < CH * CH; idx += 256) {
        float s = 0.0f;
        for (int ck = 0; ck < NCHUNK; ck++)
            s += g_pS[(size_t)(bh * NCHUNK + ck) * (CH * CH) + idx];
        sS[idx] = s;
    }
    if (tid < CH) {
        float s = 0.0f;
        for (int ck = 0; ck < NCHUNK; ck++)
            s += g_pnq[(bh * NCHUNK + ck) * CH + tid];
        snq[tid] = fmaxf(sqrtf(s), 1e-12f);
    } else if (tid >= 64 && tid < 64 + CH) {
        int d = tid - 64;
        float s = 0.0f;
        for (int ck = 0; ck < NCHUNK; ck++)
            s += g_pnk[(bh * NCHUNK + ck) * CH + d];
        snk[d] = fmaxf(sqrtf(s), 1e-12f);
    }
    __syncthreads();

    const float t = temperature[h];
    for (int idx = tid; idx < CH * CH; idx += 256) {
        int cc = idx / CH, d = idx - cc * CH;
        sS[idx] = sS[idx] * t / (snq[cc] * snk[d]);
    }
    __syncthreads();

    if (tid < CH) {
        const int cc = tid;
        float m = -1e30f;
        for (int d = 0; d < CH; d++) m = fmaxf(m, sS[cc * CH + d]);
        float sum = 0.0f;
        for (int d = 0; d < CH; d++) {
            float e = expf(sS[cc * CH + d] - m);
            sS[cc * CH + d] = e;
            sum += e;
        }
        float inv = 1.0f / sum;
        for (int d = 0; d < CH; d++)
            g_attn[(size_t)bh * (CH * CH) + cc * CH + d] = sS[cc * CH + d] * inv;
    }
}

// ---------------- attn@v fused with bf16 hi/lo split+transpose ---------------
// out[c,n] = sum_d attn[c,d] * v[d,n]; writes directly into g_xta[pixel][384]
// (head h owns bf16 columns [h*48, h*48+48) hi and [192+h*48, ...) lo).
__global__ __launch_bounds__(256) void attnv_split_kernel()
{
    const int n0 = blockIdx.x * 128;
    const int h  = blockIdx.y, b = blockIdx.z;
    const int tid = threadIdx.x;
    const int tx = tid & 31, ty = tid >> 5;

    __shared__ float sA[CH][CH];
    __shared__ __align__(16) float sV[CH][128];
    __shared__ float sO[CH][129];

    const float* vp = g_kv + ((size_t)b * C2 + C + h * CH) * HW + n0;
    const float* ap = g_attn + (size_t)(b * NH + h) * (CH * CH);

    for (int idx = tid; idx < CH * CH; idx += 256)
        sA[idx / CH][idx % CH] = ap[idx];
#pragma unroll
    for (int e = 0; e < 6; e++) {
        int idx = tid + e * 256;
        int d = idx >> 5, nv = idx & 31;
        ((float4*)(&sV[d][0]))[nv] = ((const float4*)(vp + (size_t)d * HW))[nv];
    }
    __syncthreads();

    float4 acc[6];
#pragma unroll
    for (int i = 0; i < 6; i++) acc[i] = make_float4(0.f, 0.f, 0.f, 0.f);

    for (int d = 0; d < CH; d++) {
        float4 vv = ((const float4*)(&sV[d][0]))[tx];
#pragma unroll
        for (int i = 0; i < 6; i++) {
            float a = sA[ty * 6 + i][d];
            acc[i].x += a * vv.x; acc[i].y += a * vv.y;
            acc[i].z += a * vv.z; acc[i].w += a * vv.w;
        }
    }

    // stage result [cout][pixel] in smem, then write hi/lo bf16 pairs
#pragma unroll
    for (int i = 0; i < 6; i++) {
        float* so = &sO[ty * 6 + i][tx * 4];
        so[0] = acc[i].x; so[1] = acc[i].y; so[2] = acc[i].z; so[3] = acc[i].w;
    }
    __syncthreads();

    uint32_t* xp = (uint32_t*)g_xta;
    const int hbase = h * 24;
    for (int idx = tid; idx < 128 * 48; idx += 256) {
        int p = idx / 48, u = idx - p * 48;
        int c0 = (u % 24) * 2;
        float v0 = sO[c0][p], v1 = sO[c0 + 1][p];
        __nv_bfloat16 h0 = __float2bfloat16(v0);
        __nv_bfloat16 h1 = __float2bfloat16(v1);
        uint32_t val;
        int off;
        if (u < 24) {
            val = (uint32_t)__bfloat16_as_ushort(h0)
                | ((uint32_t)__bfloat16_as_ushort(h1) << 16);
            off = hbase + u;
        } else {
            __nv_bfloat16 l0 = __float2bfloat16(v0 - __bfloat162float(h0));
            __nv_bfloat16 l1 = __float2bfloat16(v1 - __bfloat162float(h1));
            val = (uint32_t)__bfloat16_as_ushort(l0)
                | ((uint32_t)__bfloat16_as_ushort(l1) << 16);
            off = 96 + hbase + (u - 24);
        }
        xp[(size_t)(b * HW + n0 + p) * 192 + off] = val;
    }
}

// ---------------- launcher ----------------------------------------------------
extern "C" void kernel_launch(void* const* d_in, const int* in_sizes, int n_in,
                              void* d_out, int out_size)
{
    const float* x           = (const float*)d_in[0];
    const float* y           = (const float*)d_in[1];
    const float* w_qkv       = (const float*)d_in[2];
    const float* w_qkv_dw    = (const float*)d_in[3];
    const float* w_query     = (const float*)d_in[4];
    const float* w_query_dw  = (const float*)d_in[5];
    const float* w_proj      = (const float*)d_in[6];
    const float* temperature = (const float*)d_in[7];
    float* out = (float*)d_out;

    float *t1, *kv, *t2, *q;
    __nv_bfloat16 *xta, *xtb, *w1, *w2, *w3;
    cudaGetSymbolAddress((void**)&t1,  g_t1);
    cudaGetSymbolAddress((void**)&kv,  g_kv);
    cudaGetSymbolAddress((void**)&t2,  g_t2);
    cudaGetSymbolAddress((void**)&q,   g_q);
    cudaGetSymbolAddress((void**)&xta, g_xta);
    cudaGetSymbolAddress((void**)&xtb, g_xtb);
    cudaGetSymbolAddress((void**)&w1,  g_w1);
    cudaGetSymbolAddress((void**)&w2,  g_w2);
    cudaGetSymbolAddress((void**)&w3,  g_w3);

    static int smem_set = 0;
    if (!smem_set) {
        cudaFuncSetAttribute(gemm_hmma_kernel,
                             cudaFuncAttributeMaxDynamicSharedMemorySize, GSM_TOTAL);
        smem_set = 1;
    }

    // launches 0-2: weight hi/lo split (tiny)
    prep_w_kernel<<<384, 192>>>(w_qkv,   w1);
    prep_w_kernel<<<192, 192>>>(w_query, w2);
    prep_w_kernel<<<192, 192>>>(w_proj,  w3);

    // launches 3,4: activation splits (back-to-back, separate buffers)
    split_transpose_kernel<<<dim3(HW / 64, B), 256>>>(x, xta);
    split_transpose_kernel<<<dim3(HW / 64, B), 256>>>(y, xtb);

    // launch 5 (ncu -s 5 profiles this): conv1 GEMM x -> t1 [8,384,HW]
    gemm_hmma_kernel<<<dim3(HW / 128, 2, B), 256, GSM_TOTAL>>>(xta, w1, t1, 384);
    // conv2: y -> t2 [8,192,HW]
    gemm_hmma_kernel<<<dim3(HW / 128, 1, B), 256, GSM_TOTAL>>>(xtb, w2, t2, 192);

    // depthwise 3x3
    dwconv3x3_kernel<<<dim3(H / 8, C2, B), 128>>>(t1, w_qkv_dw, kv, C2);
    dwconv3x3_kernel<<<dim3(H / 8, C, B), 128>>>(t2, w_query_dw, q, C);

    // attention
    gram_kernel<<<dim3(NCHUNK, NH, B), 256>>>();
    reduce_softmax_kernel<<<B * NH, 256>>>(temperature);
    attnv_split_kernel<<<dim3(HW / 128, NH, B), 256>>>();  // writes xta (bf16)

    // conv3: att -> out
    gemm_hmma_kernel<<<dim3(HW / 128, 1, B), 256, GSM_TOTAL>>>(xta, w3, out, 192);
}

// round 7
// speedup vs baseline: 1.0446x; 1.0112x over previous
#include <cuda_runtime.h>
#include <cuda_bf16.h>
#include <math.h>
#include <stdint.h>

// Problem constants (fixed shapes)
#define B    8
#define C    192
#define C2   384
#define NH   4
#define CH   48
#define H    128
#define WD   128
#define HW   16384
#define NCHUNK 16
#define CHUNK  1024

// ---------------- scratch (static __device__ arrays) ------------------------
__device__ float g_t1 [B * C2 * HW];
__device__ float g_kv [B * C2 * HW];
__device__ float g_t2 [B * C  * HW];
__device__ float g_q  [B * C  * HW];
__device__ float g_pS [B * NH * NCHUNK * CH * CH];
__device__ float g_pnq[B * NH * NCHUNK * CH];
__device__ float g_pnk[B * NH * NCHUNK * CH];
__device__ float g_attn[B * NH * CH * CH];
// transposed bf16 hi/lo activations: [B][HW][384] (hi 0:192, lo 192:384)
__device__ __nv_bfloat16 g_xta[(size_t)B * HW * 384];  // x, later attn output
__device__ __nv_bfloat16 g_xtb[(size_t)B * HW * 384];  // y
// split weights: [Cout][384] bf16 (hi 0:192, lo 192:384)
__device__ __nv_bfloat16 g_w1[384 * 384];
__device__ __nv_bfloat16 g_w2[192 * 384];
__device__ __nv_bfloat16 g_w3[192 * 384];

// ---------------- PTX helpers (sm_103 baseline ISA only) --------------------
__device__ __forceinline__ uint32_t smem_u32(const void* p) {
    uint32_t a;
    asm("{ .reg .u64 t; cvta.to.shared.u64 t, %1; cvt.u32.u64 %0, t; }"
        : "=r"(a) : "l"(p));
    return a;
}
#define CP16(d, s) \
    asm volatile("cp.async.cg.shared.global [%0], [%1], 16;" :: "r"(d), "l"(s))
#define CP_COMMIT() asm volatile("cp.async.commit_group;")
#define CP_WAIT(n)  asm volatile("cp.async.wait_group %0;" :: "n"(n))

__device__ __forceinline__ void ldm4(uint32_t* r, uint32_t addr) {
    asm volatile("ldmatrix.sync.aligned.m8n8.x4.shared.b16 {%0,%1,%2,%3}, [%4];"
        : "=r"(r[0]), "=r"(r[1]), "=r"(r[2]), "=r"(r[3]) : "r"(addr));
}
__device__ __forceinline__ void mma_bf16(float* c, const uint32_t* a,
                                         const uint32_t* b) {
    asm volatile(
        "mma.sync.aligned.m16n8k16.row.col.f32.bf16.bf16.f32 "
        "{%0,%1,%2,%3}, {%4,%5,%6,%7}, {%8,%9}, {%0,%1,%2,%3};"
        : "+f"(c[0]), "+f"(c[1]), "+f"(c[2]), "+f"(c[3])
        : "r"(a[0]), "r"(a[1]), "r"(a[2]), "r"(a[3]), "r"(b[0]), "r"(b[1]));
}

// ---------------- weight split: W[Cout][192] -> [Cout][384] bf16 ------------
__global__ void prep_w_kernel(const float* __restrict__ w,
                              __nv_bfloat16* __restrict__ o) {
    int m = blockIdx.x;
    int k = threadIdx.x;
    float v = w[(size_t)m * 192 + k];
    __nv_bfloat16 hi = __float2bfloat16(v);
    __nv_bfloat16 lo = __float2bfloat16(v - __bfloat162float(hi));
    o[(size_t)m * 384 + k]       = hi;
    o[(size_t)m * 384 + 192 + k] = lo;
}

// ---------------- activation split+transpose: [B,192,HW] -> [B,HW,384] bf16 -
__global__ __launch_bounds__(256) void split_transpose_kernel(
    const float* __restrict__ in, __nv_bfloat16* __restrict__ out)
{
    const int n0 = blockIdx.x * 64;
    const int b  = blockIdx.y;
    __shared__ __nv_bfloat16 sT[64][390];

    const float* ip = in + (size_t)b * 192 * HW + n0;
    const int nn = threadIdx.x & 63;
    const int kq = threadIdx.x >> 6;

    for (int k0 = 0; k0 < 192; k0 += 8) {
        int k = k0 + kq * 2;
        float v0 = ip[(size_t)k * HW + nn];
        float v1 = ip[(size_t)(k + 1) * HW + nn];
        __nv_bfloat16 h0 = __float2bfloat16(v0);
        __nv_bfloat16 h1 = __float2bfloat16(v1);
        __nv_bfloat16 l0 = __float2bfloat16(v0 - __bfloat162float(h0));
        __nv_bfloat16 l1 = __float2bfloat16(v1 - __bfloat162float(h1));
        *(__nv_bfloat162*)(&sT[nn][k])       = __nv_bfloat162(h0, h1);
        *(__nv_bfloat162*)(&sT[nn][192 + k]) = __nv_bfloat162(l0, l1);
    }
    __syncthreads();

    uint32_t* op = (uint32_t*)(out + ((size_t)b * HW + n0) * 384);
    for (int idx = threadIdx.x; idx < 64 * 192; idx += 256) {
        int r = idx / 192, u = idx - r * 192;
        op[(size_t)r * 192 + u] = *(const uint32_t*)(&sT[r][u * 2]);
    }
}

// ---------------- HMMA GEMM: out[b,m,n] = sum_k W[m,k]*X[k,n] ----------------
// Block tile: 64 pixels x 192 couts, 128 threads (4 warps, each 64x48).
// Virtual K = 576 (3 hi/lo terms x 192), 18 chunks of 32.
// 3-stage cp.async ring, one barrier per iteration, 3 CTAs/SM.
#define APITCH  80
#define A_STAGE (64 * APITCH)        // 5120
#define B_STAGE (192 * APITCH)       // 15360
#define STG     (A_STAGE + B_STAGE)  // 20480
#define NSTAGE  3
#define GSM_TOTAL (NSTAGE * STG)     // 61440

__device__ __forceinline__ void g_load_chunk(
    uint32_t sb, const char* abase, const char* bbase, int tid, int c, int stage)
{
    const int term = c / 6;
    const int kk = (c - term * 6) * 32;
    const int aoff = ((term == 2 ? 192 : 0) + kk) * 2;  // X uses lo on term 2
    const int boff = ((term == 1 ? 192 : 0) + kk) * 2;  // W uses lo on term 1
    const uint32_t sa  = sb + stage * STG;
    const uint32_t sbm = sa + A_STAGE;
#pragma unroll
    for (int p = 0; p < 2; p++) {                       // A: 64 rows x 4 segs
        int idx = p * 128 + tid;
        int row = idx >> 2, q = idx & 3;
        CP16(sa + row * APITCH + q * 16,
             abase + (size_t)row * 768 + aoff + q * 16);
    }
#pragma unroll
    for (int p = 0; p < 6; p++) {                       // B: 192 rows x 4 segs
        int idx = p * 128 + tid;
        int row = idx >> 2, q = idx & 3;
        CP16(sbm + row * APITCH + q * 16,
             bbase + (size_t)row * 768 + boff + q * 16);
    }
    CP_COMMIT();
}

__global__ __launch_bounds__(128, 3) void gemm_hmma_kernel(
    const __nv_bfloat16* __restrict__ xt, const __nv_bfloat16* __restrict__ wsp,
    float* __restrict__ out, int Cout)
{
    extern __shared__ char smem[];
    const uint32_t sb = smem_u32(smem);
    const int pix0  = blockIdx.x * 64;
    const int cout0 = blockIdx.y * 192;
    const int b     = blockIdx.z;
    const int tid   = threadIdx.x;
    const int lane  = tid & 31;
    const int wx    = tid >> 5;          // cout quarter (48 each)

    const char* abase = (const char*)(xt + ((size_t)(b * HW) + pix0) * 384);
    const char* bbase = (const char*)(wsp + (size_t)cout0 * 384);

    float acc[4][6][4];
#pragma unroll
    for (int i = 0; i < 4; i++)
#pragma unroll
        for (int j = 0; j < 6; j++)
#pragma unroll
            for (int t = 0; t < 4; t++) acc[i][j][t] = 0.0f;

    g_load_chunk(sb, abase, bbase, tid, 0, 0);
    g_load_chunk(sb, abase, bbase, tid, 1, 1);

    for (int c = 0; c < 18; c++) {
        if (c + 2 < 18) {
            CP_WAIT(1);                 // chunk c landed
            __syncthreads();            // all warps done reading stage (c+2)%3
            g_load_chunk(sb, abase, bbase, tid, c + 2, (c + 2) % NSTAGE);
        } else {
            CP_WAIT(0);
            __syncthreads();
        }

        const uint32_t sa  = sb + (c % NSTAGE) * STG;
        const uint32_t sbm = sa + A_STAGE;
#pragma unroll
        for (int ks = 0; ks < 2; ks++) {
            uint32_t afr[4][4];
#pragma unroll
            for (int mi = 0; mi < 4; mi++)
                ldm4(afr[mi], sa + (mi * 16 + (lane & 15)) * APITCH
                              + ks * 32 + (lane >> 4) * 16);
            uint32_t bfr[3][4];
#pragma unroll
            for (int nj = 0; nj < 3; nj++)
                ldm4(bfr[nj], sbm + (wx * 48 + nj * 16 + (lane & 7)
                                     + (lane >> 4) * 8) * APITCH
                              + ks * 32 + ((lane >> 3) & 1) * 16);
#pragma unroll
            for (int mi = 0; mi < 4; mi++)
#pragma unroll
                for (int nj = 0; nj < 3; nj++) {
                    mma_bf16(acc[mi][nj * 2],     afr[mi], &bfr[nj][0]);
                    mma_bf16(acc[mi][nj * 2 + 1], afr[mi], &bfr[nj][2]);
                }
        }
    }

    // epilogue: direct stores (8 lanes -> 8 consecutive floats per sector)
    const int prow = lane >> 2;
    const int ccol = (lane & 3) * 2;
#pragma unroll
    for (int mi = 0; mi < 4; mi++) {
        const int p = pix0 + mi * 16 + prow;
#pragma unroll
        for (int ni = 0; ni < 6; ni++) {
            const int co = cout0 + wx * 48 + ni * 8 + ccol;
            float* o0 = out + ((size_t)b * Cout + co) * HW + p;
            o0[0]      = acc[mi][ni][0];
            o0[HW]     = acc[mi][ni][1];
            o0[8]      = acc[mi][ni][2];
            o0[HW + 8] = acc[mi][ni][3];
        }
    }
}

// ---------------- depthwise 3x3, SAME padding --------------------------------
__global__ __launch_bounds__(128) void dwconv3x3_kernel(
    const float* __restrict__ in, const float* __restrict__ w9,
    float* __restrict__ out, int Cc)
{
    const int y0 = blockIdx.x * 8;
    const int c  = blockIdx.y;
    const int b  = blockIdx.z;
    const int x  = threadIdx.x;

    __shared__ float s[10][130];
    const float* ip = in  + ((size_t)b * Cc + c) * HW;
    float*       op = out + ((size_t)b * Cc + c) * HW;

    float wr[9];
#pragma unroll
    for (int t = 0; t < 9; t++) wr[t] = w9[c * 9 + t];

#pragma unroll
    for (int r = 0; r < 10; r++) {
        int yy = y0 - 1 + r;
        s[r][x + 1] = (yy >= 0 && yy < H) ? ip[yy * WD + x] : 0.0f;
    }
    if (x == 0) {
#pragma unroll
        for (int r = 0; r < 10; r++) { s[r][0] = 0.0f; s[r][129] = 0.0f; }
    }
    __syncthreads();

#pragma unroll
    for (int ry = 0; ry < 8; ry++) {
        float a =
            s[ry + 0][x + 0] * wr[0] + s[ry + 0][x + 1] * wr[1] + s[ry + 0][x + 2] * wr[2] +
            s[ry + 1][x + 0] * wr[3] + s[ry + 1][x + 1] * wr[4] + s[ry + 1][x + 2] * wr[5] +
            s[ry + 2][x + 0] * wr[6] + s[ry + 2][x + 1] * wr[7] + s[ry + 2][x + 2] * wr[8];
        op[(y0 + ry) * WD + x] = a;
    }
}

// ---------------- split-K Gram + norms ---------------------------------------
__global__ __launch_bounds__(256) void gram_kernel()
{
    const int ck = blockIdx.x, h = blockIdx.y, b = blockIdx.z;
    const int tid = threadIdx.x;
    const int tx = tid & 15, ty = tid >> 4;

    const float* qp = g_q  + ((size_t)b * C  + h * CH) * HW + ck * CHUNK;
    const float* kp = g_kv + ((size_t)b * C2 + h * CH) * HW + ck * CHUNK;

    __shared__ float sQ[32][49];
    __shared__ float sK[32][49];

    float acc[3][3];
#pragma unroll
    for (int i = 0; i < 3; i++)
#pragma unroll
        for (int j = 0; j < 3; j++) acc[i][j] = 0.0f;
    float sq[3] = {0.f, 0.f, 0.f}, sk2[3] = {0.f, 0.f, 0.f};

    for (int nb = 0; nb < CHUNK; nb += 32) {
#pragma unroll
        for (int e = 0; e < 6; e++) {
            int idx = tid + e * 256;
            int cc = idx >> 5, nn = idx & 31;
            sQ[nn][cc] = qp[(size_t)cc * HW + nb + nn];
            sK[nn][cc] = kp[(size_t)cc * HW + nb + nn];
        }
        __syncthreads();
#pragma unroll
        for (int kk = 0; kk < 32; kk++) {
            float a0 = sQ[kk][ty * 3 + 0];
            float a1 = sQ[kk][ty * 3 + 1];
            float a2 = sQ[kk][ty * 3 + 2];
            float b0 = sK[kk][tx * 3 + 0];
            float b1 = sK[kk][tx * 3 + 1];
            float b2 = sK[kk][tx * 3 + 2];
            acc[0][0] += a0 * b0; acc[0][1] += a0 * b1; acc[0][2] += a0 * b2;
            acc[1][0] += a1 * b0; acc[1][1] += a1 * b1; acc[1][2] += a1 * b2;
            acc[2][0] += a2 * b0; acc[2][1] += a2 * b1; acc[2][2] += a2 * b2;
            if (tx == 0) { sq[0]  += a0 * a0; sq[1]  += a1 * a1; sq[2]  += a2 * a2; }
            if (ty == 0) { sk2[0] += b0 * b0; sk2[1] += b1 * b1; sk2[2] += b2 * b2; }
        }
        __syncthreads();
    }

    const int base = (b * NH + h) * NCHUNK + ck;
    float* ps = g_pS + (size_t)base * (CH * CH);
#pragma unroll
    for (int i = 0; i < 3; i++)
#pragma unroll
        for (int j = 0; j < 3; j++)
            ps[(ty * 3 + i) * CH + tx * 3 + j] = acc[i][j];
    if (tx == 0) {
#pragma unroll
        for (int i = 0; i < 3; i++) g_pnq[base * CH + ty * 3 + i] = sq[i];
    }
    if (ty == 0) {
#pragma unroll
        for (int j = 0; j < 3; j++) g_pnk[base * CH + tx * 3 + j] = sk2[j];
    }
}

// ---------------- reduce, normalize, temperature, softmax --------------------
__global__ __launch_bounds__(256) void reduce_softmax_kernel(
    const float* __restrict__ temperature)
{
    const int bh = blockIdx.x;
    const int h  = bh & (NH - 1);
    const int tid = threadIdx.x;

    __shared__ float sS[CH * CH];
    __shared__ float snq[CH], snk[CH];

    for (int idx = tid; idx < CH * CH; idx += 256) {
        float s = 0.0f;
        for (int ck = 0; ck < NCHUNK; ck++)
            s += g_pS[(size_t)(bh * NCHUNK + ck) * (CH * CH) + idx];
        sS[idx] = s;
    }
    if (tid < CH) {
        float s = 0.0f;
        for (int ck = 0; ck < NCHUNK; ck++)
            s += g_pnq[(bh * NCHUNK + ck) * CH + tid];
        snq[tid] = fmaxf(sqrtf(s), 1e-12f);
    } else if (tid >= 64 && tid < 64 + CH) {
        int d = tid - 64;
        float s = 0.0f;
        for (int ck = 0; ck < NCHUNK; ck++)
            s += g_pnk[(bh * NCHUNK + ck) * CH + d];
        snk[d] = fmaxf(sqrtf(s), 1e-12f);
    }
    __syncthreads();

    const float t = temperature[h];
    for (int idx = tid; idx < CH * CH; idx += 256) {
        int cc = idx / CH, d = idx - cc * CH;
        sS[idx] = sS[idx] * t / (snq[cc] * snk[d]);
    }
    __syncthreads();

    if (tid < CH) {
        const int cc = tid;
        float m = -1e30f;
        for (int d = 0; d < CH; d++) m = fmaxf(m, sS[cc * CH + d]);
        float sum = 0.0f;
        for (int d = 0; d < CH; d++) {
            float e = expf(sS[cc * CH + d] - m);
            sS[cc * CH + d] = e;
            sum += e;
        }
        float inv = 1.0f / sum;
        for (int d = 0; d < CH; d++)
            g_attn[(size_t)bh * (CH * CH) + cc * CH + d] = sS[cc * CH + d] * inv;
    }
}

// ---------------- attn@v fused with bf16 hi/lo split+transpose ---------------
__global__ __launch_bounds__(256) void attnv_split_kernel()
{
    const int n0 = blockIdx.x * 128;
    const int h  = blockIdx.y, b = blockIdx.z;
    const int tid = threadIdx.x;
    const int tx = tid & 31, ty = tid >> 5;

    __shared__ float sA[CH][CH];
    __shared__ __align__(16) float sV[CH][128];
    __shared__ float sO[CH][129];

    const float* vp = g_kv + ((size_t)b * C2 + C + h * CH) * HW + n0;
    const float* ap = g_attn + (size_t)(b * NH + h) * (CH * CH);

    for (int idx = tid; idx < CH * CH; idx += 256)
        sA[idx / CH][idx % CH] = ap[idx];
#pragma unroll
    for (int e = 0; e < 6; e++) {
        int idx = tid + e * 256;
        int d = idx >> 5, nv = idx & 31;
        ((float4*)(&sV[d][0]))[nv] = ((const float4*)(vp + (size_t)d * HW))[nv];
    }
    __syncthreads();

    float4 acc[6];
#pragma unroll
    for (int i = 0; i < 6; i++) acc[i] = make_float4(0.f, 0.f, 0.f, 0.f);

    for (int d = 0; d < CH; d++) {
        float4 vv = ((const float4*)(&sV[d][0]))[tx];
#pragma unroll
        for (int i = 0; i < 6; i++) {
            float a = sA[ty * 6 + i][d];
            acc[i].x += a * vv.x; acc[i].y += a * vv.y;
            acc[i].z += a * vv.z; acc[i].w += a * vv.w;
        }
    }

#pragma unroll
    for (int i = 0; i < 6; i++) {
        float* so = &sO[ty * 6 + i][tx * 4];
        so[0] = acc[i].x; so[1] = acc[i].y; so[2] = acc[i].z; so[3] = acc[i].w;
    }
    __syncthreads();

    uint32_t* xp = (uint32_t*)g_xta;
    const int hbase = h * 24;
    for (int idx = tid; idx < 128 * 48; idx += 256) {
        int p = idx / 48, u = idx - p * 48;
        int c0 = (u % 24) * 2;
        float v0 = sO[c0][p], v1 = sO[c0 + 1][p];
        __nv_bfloat16 h0 = __float2bfloat16(v0);
        __nv_bfloat16 h1 = __float2bfloat16(v1);
        uint32_t val;
        int off;
        if (u < 24) {
            val = (uint32_t)__bfloat16_as_ushort(h0)
                | ((uint32_t)__bfloat16_as_ushort(h1) << 16);
            off = hbase + u;
        } else {
            __nv_bfloat16 l0 = __float2bfloat16(v0 - __bfloat162float(h0));
            __nv_bfloat16 l1 = __float2bfloat16(v1 - __bfloat162float(h1));
            val = (uint32_t)__bfloat16_as_ushort(l0)
                | ((uint32_t)__bfloat16_as_ushort(l1) << 16);
            off = 96 + hbase + (u - 24);
        }
        xp[(size_t)(b * HW + n0 + p) * 192 + off] = val;
    }
}

// ---------------- launcher ----------------------------------------------------
extern "C" void kernel_launch(void* const* d_in, const int* in_sizes, int n_in,
                              void* d_out, int out_size)
{
    const float* x           = (const float*)d_in[0];
    const float* y           = (const float*)d_in[1];
    const float* w_qkv       = (const float*)d_in[2];
    const float* w_qkv_dw    = (const float*)d_in[3];
    const float* w_query     = (const float*)d_in[4];
    const float* w_query_dw  = (const float*)d_in[5];
    const float* w_proj      = (const float*)d_in[6];
    const float* temperature = (const float*)d_in[7];
    float* out = (float*)d_out;

    float *t1, *kv, *t2, *q;
    __nv_bfloat16 *xta, *xtb, *w1, *w2, *w3;
    cudaGetSymbolAddress((void**)&t1,  g_t1);
    cudaGetSymbolAddress((void**)&kv,  g_kv);
    cudaGetSymbolAddress((void**)&t2,  g_t2);
    cudaGetSymbolAddress((void**)&q,   g_q);
    cudaGetSymbolAddress((void**)&xta, g_xta);
    cudaGetSymbolAddress((void**)&xtb, g_xtb);
    cudaGetSymbolAddress((void**)&w1,  g_w1);
    cudaGetSymbolAddress((void**)&w2,  g_w2);
    cudaGetSymbolAddress((void**)&w3,  g_w3);

    static int smem_set = 0;
    if (!smem_set) {
        cudaFuncSetAttribute(gemm_hmma_kernel,
                             cudaFuncAttributeMaxDynamicSharedMemorySize, GSM_TOTAL);
        smem_set = 1;
    }

    // weight hi/lo split (tiny)
    prep_w_kernel<<<384, 192>>>(w_qkv,   w1);
    prep_w_kernel<<<192, 192>>>(w_query, w2);
    prep_w_kernel<<<192, 192>>>(w_proj,  w3);

    // activation splits
    split_transpose_kernel<<<dim3(HW / 64, B), 256>>>(x, xta);
    split_transpose_kernel<<<dim3(HW / 64, B), 256>>>(y, xtb);

    // conv1: x -> t1 [8,384,HW]
    gemm_hmma_kernel<<<dim3(HW / 64, 2, B), 128, GSM_TOTAL>>>(xta, w1, t1, 384);
    // conv2: y -> t2 [8,192,HW]
    gemm_hmma_kernel<<<dim3(HW / 64, 1, B), 128, GSM_TOTAL>>>(xtb, w2, t2, 192);

    // depthwise 3x3
    dwconv3x3_kernel<<<dim3(H / 8, C2, B), 128>>>(t1, w_qkv_dw, kv, C2);
    dwconv3x3_kernel<<<dim3(H / 8, C, B), 128>>>(t2, w_query_dw, q, C);

    // attention
    gram_kernel<<<dim3(NCHUNK, NH, B), 256>>>();
    reduce_softmax_kernel<<<B * NH, 256>>>(temperature);
    attnv_split_kernel<<<dim3(HW / 128, NH, B), 256>>>();  // writes xta (bf16)

    // conv3: att -> out
    gemm_hmma_kernel<<<dim3(HW / 64, 1, B), 128, GSM_TOTAL>>>(xta, w3, out, 192);
}